// round 13
// baseline (speedup 1.0000x reference)
#include <cuda_runtime.h>
#include <cuda_bf16.h>
#include <math.h>
#include <stdint.h>

#define SEQ   512
#define BATCH 64
#define HD    1024
#define OUT_MAIN ((size_t)SEQ*BATCH*HD)
#define NG    64
#define TPB   512

typedef unsigned long long u64;

#define GH_ENT 16384                    // packed h: [mt4][kb64][g8][c8]
#define GW_ENT 262144                   // packed W: [nfg128][kb64][g8][tg4]
#define GX_ENT 8388608
#define SB_ENT 4096
#define SMEM2_BYTES (4*SB_ENT*8 + 32768)
#define PC_SMEM (8192*8)

__device__ float g_P[33554432];
__device__ u64 g_h1hi[3][GH_ENT], g_h1lo[3][GH_ENT];   // triple-buffered
__device__ u64 g_h2hi[3][GH_ENT], g_h2lo[3][GH_ENT];
__device__ u64 g_Wp[3][2][GW_ENT];      // [Wh0,Wi1,Wh1][hi,lo]
__device__ u64 g_Wih[GW_ENT], g_Wil[GW_ENT];
__device__ u64 g_xph[GX_ENT], g_xpl[GX_ENT];
__device__ float g_r1[3][NG*1024];      // W1 K-partial (A -> B)
__device__ unsigned g_c1, g_c2, g_c5;

__device__ __forceinline__ uint2 ldcg2(const u64* p) {
    uint2 v;
    asm volatile("ld.global.cg.v2.u32 {%0,%1},[%2];" : "=r"(v.x), "=r"(v.y) : "l"(p));
    return v;
}
__device__ __forceinline__ void stcg64(u64* p, u64 v) {
    asm volatile("st.global.cg.u64 [%0],%1;" :: "l"(p), "l"(v));
}
__device__ __forceinline__ float4 ldcg4f(const float* p) {
    float4 v;
    asm volatile("ld.global.cg.v4.f32 {%0,%1,%2,%3},[%4];"
                 : "=f"(v.x), "=f"(v.y), "=f"(v.z), "=f"(v.w) : "l"(p));
    return v;
}
__device__ __forceinline__ void stcg4f(float* p, float4 v) {
    asm volatile("st.global.cg.v4.f32 [%0],{%1,%2,%3,%4};"
                 :: "l"(p), "f"(v.x), "f"(v.y), "f"(v.z), "f"(v.w));
}
__device__ __forceinline__ void mma16816(float d[4], uint2 a01, uint2 a23, uint2 b) {
    asm volatile(
        "mma.sync.aligned.m16n8k16.row.col.f32.bf16.bf16.f32 "
        "{%0,%1,%2,%3},{%4,%5,%6,%7},{%8,%9},{%0,%1,%2,%3};"
        : "+f"(d[0]), "+f"(d[1]), "+f"(d[2]), "+f"(d[3])
        : "r"(a01.x), "r"(a01.y), "r"(a23.x), "r"(a23.y), "r"(b.x), "r"(b.y));
}
__device__ __forceinline__ unsigned short bfu(float x) {
    return __bfloat16_as_ushort(__float2bfloat16(x));
}
__device__ __forceinline__ void pack_hilo(float v0, float v1, float v2, float v3,
                                          u64& hi, u64& lo) {
    unsigned short h0 = bfu(v0), h1 = bfu(v1), h2 = bfu(v2), h3 = bfu(v3);
    unsigned short l0 = bfu(v0 - __bfloat162float(__ushort_as_bfloat16(h0)));
    unsigned short l1 = bfu(v1 - __bfloat162float(__ushort_as_bfloat16(h1)));
    unsigned short l2 = bfu(v2 - __bfloat162float(__ushort_as_bfloat16(h2)));
    unsigned short l3 = bfu(v3 - __bfloat162float(__ushort_as_bfloat16(h3)));
    hi = (u64)h0 | ((u64)h1 << 16) | ((u64)h2 << 32) | ((u64)h3 << 48);
    lo = (u64)l0 | ((u64)l1 << 16) | ((u64)l2 << 32) | ((u64)l3 << 48);
}

// ---------------------------------------------------------------------------
__global__ void rnn_reset_kernel() {
    unsigned idx = blockIdx.x * blockDim.x + threadIdx.x;
    if (idx == 0) { g_c1 = 0u; g_c2 = 0u; g_c5 = 0u; }
    if (idx < GH_ENT) {                 // t=0 reads parity (0-1)%3 = 2
        g_h1hi[2][idx] = 0ull; g_h1lo[2][idx] = 0ull;
        g_h2hi[2][idx] = 0ull; g_h2lo[2][idx] = 0ull;
    }
}

__global__ __launch_bounds__(256)
void rnn_prepw_kernel(const float* __restrict__ Wh0, const float* __restrict__ Wi1,
                      const float* __restrict__ Wh1, const float* __restrict__ Wi0)
{
    unsigned idx = blockIdx.x * blockDim.x + threadIdx.x;
    if (idx >= 4u * GW_ENT) return;
    const int m = idx / GW_ENT;
    const unsigned e = idx % GW_ENT;
    const int nfg = e >> 11, kb = (e >> 5) & 63, gg = (e >> 2) & 7, tg = e & 3;
    const float* W = (m == 0) ? Wh0 : (m == 1) ? Wi1 : (m == 2) ? Wh1 : Wi0;
    const float* p = W + (size_t)(nfg * 8 + gg) * HD + kb * 16 + tg * 2;
    u64 hi, lo;
    pack_hilo(p[0], p[1], p[8], p[9], hi, lo);
    if (m < 3) { g_Wp[m][0][e] = hi; g_Wp[m][1][e] = lo; }
    else       { g_Wih[e] = hi;      g_Wil[e] = lo; }
}

__global__ __launch_bounds__(256)
void rnn_xpack_kernel(const float* __restrict__ X)
{
    unsigned e = blockIdx.x * blockDim.x + threadIdx.x;
    if (e >= GX_ENT) return;
    const int c = e & 7, gg = (e >> 3) & 7, kb = (e >> 6) & 63, mt = e >> 12;
    const int k = kb * 16 + ((c < 4) ? c * 2 : 8 + (c - 4) * 2);
    const int r0 = mt * 16 + gg;
    const float2 v01 = *(const float2*)&X[(size_t)r0 * HD + k];
    const float2 v23 = *(const float2*)&X[(size_t)(r0 + 8) * HD + k];
    u64 hi, lo;
    pack_hilo(v01.x, v01.y, v23.x, v23.y, hi, lo);
    g_xph[e] = hi; g_xpl[e] = lo;
}

// ---------------------------------------------------------------------------
// precompute via bf16-pair MMA, 2 M-tiles per warp (halved B-LDS traffic)
// grid (16 n-tiles, 128 y); warp handles mt0 = 2*(by*8+wid), mt0+1
// ---------------------------------------------------------------------------
__device__ __forceinline__ void pc_stageB(u64* sbase, int ntile, int ch, int tid) {
#pragma unroll
    for (int i = 0; i < 8; i++) {
        const int u = tid + i * 256;
        const int prec = u >> 10, r = u & 1023, nfg = r >> 7, off = (r & 127) * 2;
        const u64* src = (prec ? g_Wil : g_Wih)
                       + ((size_t)(ntile * 8 + nfg) * 64 + ch * 8) * 32 + off;
        unsigned ds = (unsigned)__cvta_generic_to_shared(
            sbase + prec * 2048 + nfg * 256 + off);
        asm volatile("cp.async.cg.shared.global [%0],[%1],16;" :: "r"(ds), "l"(src));
    }
}

__global__ __launch_bounds__(256)
void rnn_precompute_mma(const float* __restrict__ bi0, const float* __restrict__ bh0)
{
    extern __shared__ u64 sB[];                    // 2 x 4096 entries
    const int tid = threadIdx.x, wid = tid >> 5, lane = tid & 31;
    const int gg = lane >> 2, tg = lane & 3;
    const int ntile = blockIdx.x;
    const int mt0 = (blockIdx.y * 8 + wid) * 2;    // tiles mt0, mt0+1

    float D[16][4];                                 // [mi*8+nf]
#pragma unroll
    for (int q = 0; q < 16; q++)
        D[q][0] = D[q][1] = D[q][2] = D[q][3] = 0.f;

    pc_stageB(sB, ntile, 0, tid);
    asm volatile("cp.async.commit_group;" ::: "memory");

    uint2 Ah01[3][2], Ah23[3][2], Al01[3][2], Al23[3][2];
#define PCLOADA(s, kb) { \
    _Pragma("unroll") \
    for (int mi = 0; mi < 2; mi++) { \
        const size_t b_ = ((size_t)((mt0 + mi) * 64 + (kb)) << 6) + (gg << 3) + tg; \
        Ah01[s][mi] = ldcg2(g_xph + b_); Ah23[s][mi] = ldcg2(g_xph + b_ + 4); \
        Al01[s][mi] = ldcg2(g_xpl + b_); Al23[s][mi] = ldcg2(g_xpl + b_ + 4); } }
    PCLOADA(0, 0); PCLOADA(1, 1);

    for (int ch = 0; ch < 8; ch++) {
        if (ch + 1 < 8) {
            pc_stageB(sB + ((ch + 1) & 1) * 4096, ntile, ch + 1, tid);
            asm volatile("cp.async.commit_group;" ::: "memory");
            asm volatile("cp.async.wait_group 1;" ::: "memory");
        } else {
            asm volatile("cp.async.wait_group 0;" ::: "memory");
        }
        __syncthreads();
        const u64* bufp = sB + (ch & 1) * 4096;
#pragma unroll
        for (int kl = 0; kl < 8; kl++) {
            const int kb = ch * 8 + kl;
            if (kb + 2 < 64) PCLOADA((kb + 2) % 3, kb + 2);
            const int c = kb % 3;
            uint2 Bh[8], Bl[8];
#pragma unroll
            for (int nf = 0; nf < 8; nf++) {
                Bh[nf] = *(const uint2*)(bufp + nf * 256 + kl * 32 + lane);
                Bl[nf] = *(const uint2*)(bufp + 2048 + nf * 256 + kl * 32 + lane);
            }
#pragma unroll
            for (int nf = 0; nf < 8; nf++) {
                mma16816(D[nf],     Ah01[c][0], Ah23[c][0], Bh[nf]);
                mma16816(D[8 + nf], Ah01[c][1], Ah23[c][1], Bh[nf]);
            }
#pragma unroll
            for (int nf = 0; nf < 8; nf++) {
                mma16816(D[nf],     Ah01[c][0], Ah23[c][0], Bl[nf]);
                mma16816(D[8 + nf], Ah01[c][1], Ah23[c][1], Bl[nf]);
            }
#pragma unroll
            for (int nf = 0; nf < 8; nf++) {
                mma16816(D[nf],     Al01[c][0], Al23[c][0], Bh[nf]);
                mma16816(D[8 + nf], Al01[c][1], Al23[c][1], Bh[nf]);
            }
        }
        __syncthreads();
    }
#undef PCLOADA

#pragma unroll
    for (int mi = 0; mi < 2; mi++) {
        const int r0 = (mt0 + mi) * 16 + gg;
#pragma unroll
        for (int nf = 0; nf < 8; nf++) {
            const int n0 = ntile * 64 + nf * 8 + tg * 2;
            const float b0 = bi0[n0] + bh0[n0], b1 = bi0[n0 + 1] + bh0[n0 + 1];
            const float* d = D[mi * 8 + nf];
            *(float2*)&g_P[(size_t)r0 * HD + n0]       = make_float2(d[0] + b0, d[1] + b1);
            *(float2*)&g_P[(size_t)(r0 + 8) * HD + n0] = make_float2(d[2] + b0, d[3] + b1);
        }
    }
}

// ---------------------------------------------------------------------------
// grid sync (R10-proven primitives)
// ---------------------------------------------------------------------------
__device__ __forceinline__ void grid_arrive(unsigned* c) {
    __threadfence();
    __syncthreads();
    if (threadIdx.x == 0) atomicAdd(c, 1u);
}
__device__ __forceinline__ void grid_wait(unsigned* c, unsigned target) {
    if (threadIdx.x == 0) {
        while (*((volatile unsigned*)c) < target) __nanosleep(16);
        __threadfence();
    }
    __syncthreads();
}

// warp GEMM slice over NJ kb-iterations starting at kb0
template<int NJ>
__device__ __forceinline__ void gemm_acc(float (&D)[4][4],
    const u64* __restrict__ ghHi, const u64* __restrict__ ghLo,
    const u64* __restrict__ sBhi, int kb0, int mbase, int gg, int tg)
{
    uint2 Ah01[3][2], Ah23[3][2], Al01[3][2], Al23[3][2];
#pragma unroll
    for (int p = 0; p < 2; p++)
#pragma unroll
        for (int mi = 0; mi < 2; mi++) {
            const size_t b = ((size_t)((mbase+mi)*64 + kb0 + p) << 6) + (gg<<3) + tg;
            Ah01[p][mi] = ldcg2(ghHi+b);  Ah23[p][mi] = ldcg2(ghHi+b+4);
            Al01[p][mi] = ldcg2(ghLo+b);  Al23[p][mi] = ldcg2(ghLo+b+4);
        }
    uint2 Bh0[2], Bh1[2], Bl0[2], Bl1[2];
    {
        const int bi = (kb0 << 5) + (gg << 2) + tg;
        Bh0[0] = *(const uint2*)(sBhi + bi);
        Bh1[0] = *(const uint2*)(sBhi + 2048 + bi);
        Bl0[0] = *(const uint2*)(sBhi + SB_ENT + bi);
        Bl1[0] = *(const uint2*)(sBhi + SB_ENT + 2048 + bi);
    }
#pragma unroll
    for (int j = 0; j < NJ; j++) {
        const int cb = j & 1, nb = cb ^ 1;
        if (j < NJ - 1) {
            const int bi = ((kb0 + j + 1) << 5) + (gg << 2) + tg;
            Bh0[nb] = *(const uint2*)(sBhi + bi);
            Bh1[nb] = *(const uint2*)(sBhi + 2048 + bi);
            Bl0[nb] = *(const uint2*)(sBhi + SB_ENT + bi);
            Bl1[nb] = *(const uint2*)(sBhi + SB_ENT + 2048 + bi);
        }
        if (j + 2 < NJ) {
            const int s = (j + 2) % 3;
#pragma unroll
            for (int mi = 0; mi < 2; mi++) {
                const size_t b = ((size_t)((mbase+mi)*64 + kb0 + j + 2) << 6) + (gg<<3) + tg;
                Ah01[s][mi] = ldcg2(ghHi+b);  Ah23[s][mi] = ldcg2(ghHi+b+4);
                Al01[s][mi] = ldcg2(ghLo+b);  Al23[s][mi] = ldcg2(ghLo+b+4);
            }
        }
        const int c = j % 3;
        mma16816(D[0], Ah01[c][0], Ah23[c][0], Bh0[cb]);
        mma16816(D[1], Ah01[c][0], Ah23[c][0], Bh1[cb]);
        mma16816(D[2], Ah01[c][1], Ah23[c][1], Bh0[cb]);
        mma16816(D[3], Ah01[c][1], Ah23[c][1], Bh1[cb]);
        mma16816(D[0], Ah01[c][0], Ah23[c][0], Bl0[cb]);
        mma16816(D[1], Ah01[c][0], Ah23[c][0], Bl1[cb]);
        mma16816(D[2], Ah01[c][1], Ah23[c][1], Bl0[cb]);
        mma16816(D[3], Ah01[c][1], Ah23[c][1], Bl1[cb]);
        mma16816(D[0], Al01[c][0], Al23[c][0], Bh0[cb]);
        mma16816(D[1], Al01[c][0], Al23[c][0], Bh1[cb]);
        mma16816(D[2], Al01[c][1], Al23[c][1], Bh0[cb]);
        mma16816(D[3], Al01[c][1], Al23[c][1], Bh1[cb]);
    }
}

__device__ __forceinline__ void kredw(const float (&D)[4][4], float* sred,
                                      int kw, int mbase, int lane)
{
    const int sw = lane & 7;
#pragma unroll
    for (int ui = 0; ui < 4; ui++) {
        const int u = (mbase + (ui >> 1)) * 2 + (ui & 1);
        float4* p = (float4*)&sred[((((u*32+lane) << 3) + (kw ^ sw)) << 2)];
        *p = make_float4(D[ui][0], D[ui][1], D[ui][2], D[ui][3]);
    }
}
__device__ __forceinline__ void kredr(const float* sred, int u, int lane, float r[4]) {
    const int sw = lane & 7;
    r[0] = r[1] = r[2] = r[3] = 0.f;
#pragma unroll
    for (int w = 0; w < 8; w++) {
        float4 v = *(const float4*)&sred[((((u*32+lane) << 3) + (w ^ sw)) << 2)];
        r[0] += v.x; r[1] += v.y; r[2] += v.z; r[3] += v.w;
    }
}

// ---------------------------------------------------------------------------
// pipeline-parallel recurrent, triple-buffered state. W1 split A:3/8, B:5/8.
// counters: c1 h1 published | c2 h2 published | c5 A's W1 partial published
// ---------------------------------------------------------------------------
__global__ __launch_bounds__(TPB)
void rnn_recurrent_kernel(const float* __restrict__ bi1,
                          const float* __restrict__ bh1,
                          float* __restrict__ out,
                          int write_final)
{
    extern __shared__ u64 smem_u64[];
    u64*   sB   = smem_u64;
    float* sred = (float*)(smem_u64 + 4*SB_ENT);

    const int tid  = threadIdx.x;
    const int wid  = tid >> 5;
    const int lane = tid & 31;
    const int gg   = lane >> 2;
    const int tg   = lane & 3;
    const int grpB = (blockIdx.x >= NG);
    const int cta  = grpB ? (blockIdx.x - NG) : blockIdx.x;
    const int kw   = wid >> 1;
    const int mbase = (wid & 1) * 2;

    // A: slots 0,1 = Wh0 hi/lo; slots 2,3 = Wi1 hi/lo.
    // B: slots 0,1 = Wi1 hi/lo; slots 2,3 = Wh1 hi/lo.
#pragma unroll
    for (int mp = 0; mp < 4; mp++) {
        const int mat = grpB ? ((mp >> 1) + 1) : (mp >> 1);
        const u64* src = g_Wp[mat][mp & 1] + (size_t)cta * SB_ENT;
        u64* dst = sB + mp * SB_ENT;
        for (int i = tid * 2; i < SB_ENT; i += TPB * 2)
            *(uint4*)(dst + i) = *(const uint4*)(src + i);
    }

    const int u  = wid & 7;
    const int mt = u >> 1, nf = u & 1;
    const int m0 = mt * 16 + gg;
    const int n0 = cta * 16 + nf * 8 + tg * 2;
    const unsigned ei = (unsigned)((mt * 64 + cta) << 6) + (gg << 3) + (nf * 4 + tg);
    const unsigned pi = ((unsigned)cta << 10) + ((unsigned)u << 7) + ((unsigned)lane << 2);
    const float bias0 = bi1[n0] + bh1[n0];
    const float bias1 = bi1[n0+1] + bh1[n0+1];
    __syncthreads();

    float D[4][4], r[4];

    if (!grpB) {
        // ------------- group A: W0 (full K) + W1 kb 0..23 -------------
        for (int t = 0; t < SEQ; t++) {
            const int rp = (t + 2) % 3, wp = t % 3;
            // prefetch P(t) early (off the epilogue critical path)
            float2 pf0, pf1;
            if (wid < 8) {
                const float* Pt = g_P + (size_t)t * BATCH * HD;
                pf0 = __ldg((const float2*)(Pt + (size_t)m0 * HD + n0));
                pf1 = __ldg((const float2*)(Pt + (size_t)(m0+8) * HD + n0));
            }
#pragma unroll
            for (int ui = 0; ui < 4; ui++)
                D[ui][0] = D[ui][1] = D[ui][2] = D[ui][3] = 0.f;
            gemm_acc<8>(D, g_h1hi[rp], g_h1lo[rp], sB, kw * 8, mbase, gg, tg);
            kredw(D, sred, kw, mbase, lane);
            // slack wait: B's epi(t-3) done -> h1[wp], g_r1[wp] reusable
            grid_wait(&g_c2, (t >= 2) ? (unsigned)(t - 2) * NG : 0u);
            __syncthreads();
            if (wid < 8) {
                kredr(sred, u, lane, r);
                float v0 = tanhf(r[0] + pf0.x), v1 = tanhf(r[1] + pf0.y);
                float v2 = tanhf(r[2] + pf1.x), v3 = tanhf(r[3] + pf1.y);
                u64 hi, lo; pack_hilo(v0, v1, v2, v3, hi, lo);
                stcg64(&g_h1hi[wp][ei], hi);
                stcg64(&g_h1lo[wp][ei], lo);
                if (write_final && t == SEQ - 1) {
                    *(float2*)&out[OUT_MAIN + (size_t)m0*HD + n0]     = make_float2(v0, v1);
                    *(float2*)&out[OUT_MAIN + (size_t)(m0+8)*HD + n0] = make_float2(v2, v3);
                }
            }
            grid_arrive(&g_c1);                      // publish h1(t)
            grid_wait(&g_c1, (unsigned)(t + 1) * NG);
#pragma unroll
            for (int ui = 0; ui < 4; ui++)
                D[ui][0] = D[ui][1] = D[ui][2] = D[ui][3] = 0.f;
            gemm_acc<3>(D, g_h1hi[wp], g_h1lo[wp], sB + 2*SB_ENT, kw * 3, mbase, gg, tg);
            kredw(D, sred, kw, mbase, lane);
            __syncthreads();
            if (wid < 8) {
                kredr(sred, u, lane, r);
                stcg4f(&g_r1[wp][pi], make_float4(r[0], r[1], r[2], r[3]));
            }
            grid_arrive(&g_c5);                      // publish W1 partial(t)
        }
    } else {
        // ------------- group B: W2 (full K) + W1 kb 24..63 -------------
        for (int t = 0; t < SEQ; t++) {
            const int rp = (t + 2) % 3, wp = t % 3;
            grid_wait(&g_c2, (unsigned)t * NG);      // all B epi(t-1) done
#pragma unroll
            for (int ui = 0; ui < 4; ui++)
                D[ui][0] = D[ui][1] = D[ui][2] = D[ui][3] = 0.f;
            gemm_acc<8>(D, g_h2hi[rp], g_h2lo[rp], sB + 2*SB_ENT, kw * 8, mbase, gg, tg);
            grid_wait(&g_c1, (unsigned)(t + 1) * NG);// h1(t) visible
            gemm_acc<5>(D, g_h1hi[wp], g_h1lo[wp], sB, 24 + kw * 5, mbase, gg, tg);
            kredw(D, sred, kw, mbase, lane);
            grid_wait(&g_c5, (unsigned)(t + 1) * NG);// A's partial(t) ready
            __syncthreads();
            if (wid < 8) {
                kredr(sred, u, lane, r);
                const float4 pa = ldcg4f(&g_r1[wp][pi]);
                float v0 = tanhf(r[0] + pa.x + bias0), v1 = tanhf(r[1] + pa.y + bias1);
                float v2 = tanhf(r[2] + pa.z + bias0), v3 = tanhf(r[3] + pa.w + bias1);
                u64 hi, lo; pack_hilo(v0, v1, v2, v3, hi, lo);
                stcg64(&g_h2hi[wp][ei], hi);
                stcg64(&g_h2lo[wp][ei], lo);
                float* ot = out + (size_t)t * BATCH * HD;
                *(float2*)&ot[(size_t)m0*HD + n0]     = make_float2(v0, v1);
                *(float2*)&ot[(size_t)(m0+8)*HD + n0] = make_float2(v2, v3);
                if (write_final && t == SEQ - 1) {
                    float* hf = out + OUT_MAIN + (size_t)BATCH*HD;
                    *(float2*)&hf[(size_t)m0*HD + n0]     = make_float2(v0, v1);
                    *(float2*)&hf[(size_t)(m0+8)*HD + n0] = make_float2(v2, v3);
                }
            }
            grid_arrive(&g_c2);                      // publish h2(t)
        }
    }
}

// ---------------------------------------------------------------------------
extern "C" void kernel_launch(void* const* d_in, const int* in_sizes, int n_in,
                              void* d_out, int out_size) {
    const float* x   = (const float*)d_in[0];
    const float* Wi0 = (const float*)d_in[1];
    const float* bi0 = (const float*)d_in[2];
    const float* Wh0 = (const float*)d_in[3];
    const float* bh0 = (const float*)d_in[4];
    const float* Wi1 = (const float*)d_in[5];
    const float* bi1 = (const float*)d_in[6];
    const float* Wh1 = (const float*)d_in[7];
    const float* bh1 = (const float*)d_in[8];
    float* out = (float*)d_out;

    const int write_final =
        ((size_t)out_size >= OUT_MAIN + (size_t)2 * BATCH * HD) ? 1 : 0;

    cudaFuncSetAttribute(rnn_recurrent_kernel,
                         cudaFuncAttributeMaxDynamicSharedMemorySize, SMEM2_BYTES);
    cudaFuncSetAttribute(rnn_precompute_mma,
                         cudaFuncAttributeMaxDynamicSharedMemorySize, PC_SMEM);

    rnn_reset_kernel<<<256, 256>>>();
    rnn_prepw_kernel<<<(4*GW_ENT + 255)/256, 256>>>(Wh0, Wi1, Wh1, Wi0);
    rnn_xpack_kernel<<<(GX_ENT + 255)/256, 256>>>(x);
    rnn_precompute_mma<<<dim3(16, 128), 256, PC_SMEM>>>(bi0, bh0);
    rnn_recurrent_kernel<<<2*NG, TPB, SMEM2_BYTES>>>(bi1, bh1, out, write_final);
}

// round 14
// speedup vs baseline: 1.0563x; 1.0563x over previous
#include <cuda_runtime.h>
#include <cuda_bf16.h>
#include <math.h>
#include <stdint.h>

#define SEQ   512
#define BATCH 64
#define HD    1024
#define OUT_MAIN ((size_t)SEQ*BATCH*HD)
#define NG    64
#define TPB   512

typedef unsigned long long u64;

#define GH_ENT 16384                    // packed h: [mt4][kb64][g8][c8]
#define GW_ENT 262144                   // packed W: [nfg128][kb64][g8][tg4]
#define GX_ENT 8388608
#define SB_ENT 4096
#define SMEM2_BYTES (4*SB_ENT*8 + 32768)
#define PC_SMEM (8192*8)

__device__ float g_P[33554432];
__device__ u64 g_h1hi[3][GH_ENT], g_h1lo[3][GH_ENT];   // triple-buffered
__device__ u64 g_h2hi[3][GH_ENT], g_h2lo[3][GH_ENT];
__device__ u64 g_Wp[3][2][GW_ENT];      // [Wh0,Wi1,Wh1][hi,lo]
__device__ u64 g_Wih[GW_ENT], g_Wil[GW_ENT];
__device__ u64 g_xph[GX_ENT], g_xpl[GX_ENT];
__device__ float g_r1[3][NG*1024];      // W1 K-half partials (A -> B)
__device__ unsigned g_c1, g_c2, g_c5;

__device__ __forceinline__ uint2 ldcg2(const u64* p) {
    uint2 v;
    asm volatile("ld.global.cg.v2.u32 {%0,%1},[%2];" : "=r"(v.x), "=r"(v.y) : "l"(p));
    return v;
}
__device__ __forceinline__ void stcg64(u64* p, u64 v) {
    asm volatile("st.global.cg.u64 [%0],%1;" :: "l"(p), "l"(v));
}
__device__ __forceinline__ float4 ldcg4f(const float* p) {
    float4 v;
    asm volatile("ld.global.cg.v4.f32 {%0,%1,%2,%3},[%4];"
                 : "=f"(v.x), "=f"(v.y), "=f"(v.z), "=f"(v.w) : "l"(p));
    return v;
}
__device__ __forceinline__ void stcg4f(float* p, float4 v) {
    asm volatile("st.global.cg.v4.f32 [%0],{%1,%2,%3,%4};"
                 :: "l"(p), "f"(v.x), "f"(v.y), "f"(v.z), "f"(v.w));
}
__device__ __forceinline__ void mma16816(float d[4], uint2 a01, uint2 a23, uint2 b) {
    asm volatile(
        "mma.sync.aligned.m16n8k16.row.col.f32.bf16.bf16.f32 "
        "{%0,%1,%2,%3},{%4,%5,%6,%7},{%8,%9},{%0,%1,%2,%3};"
        : "+f"(d[0]), "+f"(d[1]), "+f"(d[2]), "+f"(d[3])
        : "r"(a01.x), "r"(a01.y), "r"(a23.x), "r"(a23.y), "r"(b.x), "r"(b.y));
}
__device__ __forceinline__ unsigned short bfu(float x) {
    return __bfloat16_as_ushort(__float2bfloat16(x));
}
__device__ __forceinline__ void pack_hilo(float v0, float v1, float v2, float v3,
                                          u64& hi, u64& lo) {
    unsigned short h0 = bfu(v0), h1 = bfu(v1), h2 = bfu(v2), h3 = bfu(v3);
    unsigned short l0 = bfu(v0 - __bfloat162float(__ushort_as_bfloat16(h0)));
    unsigned short l1 = bfu(v1 - __bfloat162float(__ushort_as_bfloat16(h1)));
    unsigned short l2 = bfu(v2 - __bfloat162float(__ushort_as_bfloat16(h2)));
    unsigned short l3 = bfu(v3 - __bfloat162float(__ushort_as_bfloat16(h3)));
    hi = (u64)h0 | ((u64)h1 << 16) | ((u64)h2 << 32) | ((u64)h3 << 48);
    lo = (u64)l0 | ((u64)l1 << 16) | ((u64)l2 << 32) | ((u64)l3 << 48);
}

// ---------------------------------------------------------------------------
__global__ void rnn_reset_kernel() {
    unsigned idx = blockIdx.x * blockDim.x + threadIdx.x;
    if (idx == 0) { g_c1 = 0u; g_c2 = 0u; g_c5 = 0u; }
    if (idx < GH_ENT) {                 // t=0 reads parity (0-1)%3 = 2
        g_h1hi[2][idx] = 0ull; g_h1lo[2][idx] = 0ull;
        g_h2hi[2][idx] = 0ull; g_h2lo[2][idx] = 0ull;
    }
}

__global__ __launch_bounds__(256)
void rnn_prepw_kernel(const float* __restrict__ Wh0, const float* __restrict__ Wi1,
                      const float* __restrict__ Wh1, const float* __restrict__ Wi0)
{
    unsigned idx = blockIdx.x * blockDim.x + threadIdx.x;
    if (idx >= 4u * GW_ENT) return;
    const int m = idx / GW_ENT;
    const unsigned e = idx % GW_ENT;
    const int nfg = e >> 11, kb = (e >> 5) & 63, gg = (e >> 2) & 7, tg = e & 3;
    const float* W = (m == 0) ? Wh0 : (m == 1) ? Wi1 : (m == 2) ? Wh1 : Wi0;
    const float* p = W + (size_t)(nfg * 8 + gg) * HD + kb * 16 + tg * 2;
    u64 hi, lo;
    pack_hilo(p[0], p[1], p[8], p[9], hi, lo);
    if (m < 3) { g_Wp[m][0][e] = hi; g_Wp[m][1][e] = lo; }
    else       { g_Wih[e] = hi;      g_Wil[e] = lo; }
}

__global__ __launch_bounds__(256)
void rnn_xpack_kernel(const float* __restrict__ X)
{
    unsigned e = blockIdx.x * blockDim.x + threadIdx.x;
    if (e >= GX_ENT) return;
    const int c = e & 7, gg = (e >> 3) & 7, kb = (e >> 6) & 63, mt = e >> 12;
    const int k = kb * 16 + ((c < 4) ? c * 2 : 8 + (c - 4) * 2);
    const int r0 = mt * 16 + gg;
    const float2 v01 = *(const float2*)&X[(size_t)r0 * HD + k];
    const float2 v23 = *(const float2*)&X[(size_t)(r0 + 8) * HD + k];
    u64 hi, lo;
    pack_hilo(v01.x, v01.y, v23.x, v23.y, hi, lo);
    g_xph[e] = hi; g_xpl[e] = lo;
}

// ---------------------------------------------------------------------------
// precompute via bf16-pair MMA, 2 M-tiles per warp (R13-proven, 768us)
// ---------------------------------------------------------------------------
__device__ __forceinline__ void pc_stageB(u64* sbase, int ntile, int ch, int tid) {
#pragma unroll
    for (int i = 0; i < 8; i++) {
        const int u = tid + i * 256;
        const int prec = u >> 10, r = u & 1023, nfg = r >> 7, off = (r & 127) * 2;
        const u64* src = (prec ? g_Wil : g_Wih)
                       + ((size_t)(ntile * 8 + nfg) * 64 + ch * 8) * 32 + off;
        unsigned ds = (unsigned)__cvta_generic_to_shared(
            sbase + prec * 2048 + nfg * 256 + off);
        asm volatile("cp.async.cg.shared.global [%0],[%1],16;" :: "r"(ds), "l"(src));
    }
}

__global__ __launch_bounds__(256)
void rnn_precompute_mma(const float* __restrict__ bi0, const float* __restrict__ bh0)
{
    extern __shared__ u64 sB[];                    // 2 x 4096 entries
    const int tid = threadIdx.x, wid = tid >> 5, lane = tid & 31;
    const int gg = lane >> 2, tg = lane & 3;
    const int ntile = blockIdx.x;
    const int mt0 = (blockIdx.y * 8 + wid) * 2;    // tiles mt0, mt0+1

    float D[16][4];                                 // [mi*8+nf]
#pragma unroll
    for (int q = 0; q < 16; q++)
        D[q][0] = D[q][1] = D[q][2] = D[q][3] = 0.f;

    pc_stageB(sB, ntile, 0, tid);
    asm volatile("cp.async.commit_group;" ::: "memory");

    uint2 Ah01[3][2], Ah23[3][2], Al01[3][2], Al23[3][2];
#define PCLOADA(s, kb) { \
    _Pragma("unroll") \
    for (int mi = 0; mi < 2; mi++) { \
        const size_t b_ = ((size_t)((mt0 + mi) * 64 + (kb)) << 6) + (gg << 3) + tg; \
        Ah01[s][mi] = ldcg2(g_xph + b_); Ah23[s][mi] = ldcg2(g_xph + b_ + 4); \
        Al01[s][mi] = ldcg2(g_xpl + b_); Al23[s][mi] = ldcg2(g_xpl + b_ + 4); } }
    PCLOADA(0, 0); PCLOADA(1, 1);

    for (int ch = 0; ch < 8; ch++) {
        if (ch + 1 < 8) {
            pc_stageB(sB + ((ch + 1) & 1) * 4096, ntile, ch + 1, tid);
            asm volatile("cp.async.commit_group;" ::: "memory");
            asm volatile("cp.async.wait_group 1;" ::: "memory");
        } else {
            asm volatile("cp.async.wait_group 0;" ::: "memory");
        }
        __syncthreads();
        const u64* bufp = sB + (ch & 1) * 4096;
#pragma unroll
        for (int kl = 0; kl < 8; kl++) {
            const int kb = ch * 8 + kl;
            if (kb + 2 < 64) PCLOADA((kb + 2) % 3, kb + 2);
            const int c = kb % 3;
            uint2 Bh[8], Bl[8];
#pragma unroll
            for (int nf = 0; nf < 8; nf++) {
                Bh[nf] = *(const uint2*)(bufp + nf * 256 + kl * 32 + lane);
                Bl[nf] = *(const uint2*)(bufp + 2048 + nf * 256 + kl * 32 + lane);
            }
#pragma unroll
            for (int nf = 0; nf < 8; nf++) {
                mma16816(D[nf],     Ah01[c][0], Ah23[c][0], Bh[nf]);
                mma16816(D[8 + nf], Ah01[c][1], Ah23[c][1], Bh[nf]);
            }
#pragma unroll
            for (int nf = 0; nf < 8; nf++) {
                mma16816(D[nf],     Ah01[c][0], Ah23[c][0], Bl[nf]);
                mma16816(D[8 + nf], Ah01[c][1], Ah23[c][1], Bl[nf]);
            }
#pragma unroll
            for (int nf = 0; nf < 8; nf++) {
                mma16816(D[nf],     Al01[c][0], Al23[c][0], Bh[nf]);
                mma16816(D[8 + nf], Al01[c][1], Al23[c][1], Bh[nf]);
            }
        }
        __syncthreads();
    }
#undef PCLOADA

#pragma unroll
    for (int mi = 0; mi < 2; mi++) {
        const int r0 = (mt0 + mi) * 16 + gg;
#pragma unroll
        for (int nf = 0; nf < 8; nf++) {
            const int n0 = ntile * 64 + nf * 8 + tg * 2;
            const float b0 = bi0[n0] + bh0[n0], b1 = bi0[n0 + 1] + bh0[n0 + 1];
            const float* d = D[mi * 8 + nf];
            *(float2*)&g_P[(size_t)r0 * HD + n0]       = make_float2(d[0] + b0, d[1] + b1);
            *(float2*)&g_P[(size_t)(r0 + 8) * HD + n0] = make_float2(d[2] + b0, d[3] + b1);
        }
    }
}

// ---------------------------------------------------------------------------
// grid sync (R10-proven primitives)
// ---------------------------------------------------------------------------
__device__ __forceinline__ void grid_arrive(unsigned* c) {
    __threadfence();
    __syncthreads();
    if (threadIdx.x == 0) atomicAdd(c, 1u);
}
__device__ __forceinline__ void grid_wait(unsigned* c, unsigned target) {
    if (threadIdx.x == 0) {
        while (*((volatile unsigned*)c) < target) __nanosleep(16);
        __threadfence();
    }
    __syncthreads();
}

// warp GEMM slice over NJ kb-iterations starting at kb0
template<int NJ>
__device__ __forceinline__ void gemm_acc(float (&D)[4][4],
    const u64* __restrict__ ghHi, const u64* __restrict__ ghLo,
    const u64* __restrict__ sBhi, int kb0, int mbase, int gg, int tg)
{
    uint2 Ah01[3][2], Ah23[3][2], Al01[3][2], Al23[3][2];
#pragma unroll
    for (int p = 0; p < 2; p++)
#pragma unroll
        for (int mi = 0; mi < 2; mi++) {
            const size_t b = ((size_t)((mbase+mi)*64 + kb0 + p) << 6) + (gg<<3) + tg;
            Ah01[p][mi] = ldcg2(ghHi+b);  Ah23[p][mi] = ldcg2(ghHi+b+4);
            Al01[p][mi] = ldcg2(ghLo+b);  Al23[p][mi] = ldcg2(ghLo+b+4);
        }
    uint2 Bh0[2], Bh1[2], Bl0[2], Bl1[2];
    {
        const int bi = (kb0 << 5) + (gg << 2) + tg;
        Bh0[0] = *(const uint2*)(sBhi + bi);
        Bh1[0] = *(const uint2*)(sBhi + 2048 + bi);
        Bl0[0] = *(const uint2*)(sBhi + SB_ENT + bi);
        Bl1[0] = *(const uint2*)(sBhi + SB_ENT + 2048 + bi);
    }
#pragma unroll
    for (int j = 0; j < NJ; j++) {
        const int cb = j & 1, nb = cb ^ 1;
        if (j < NJ - 1) {
            const int bi = ((kb0 + j + 1) << 5) + (gg << 2) + tg;
            Bh0[nb] = *(const uint2*)(sBhi + bi);
            Bh1[nb] = *(const uint2*)(sBhi + 2048 + bi);
            Bl0[nb] = *(const uint2*)(sBhi + SB_ENT + bi);
            Bl1[nb] = *(const uint2*)(sBhi + SB_ENT + 2048 + bi);
        }
        if (j + 2 < NJ) {
            const int s = (j + 2) % 3;
#pragma unroll
            for (int mi = 0; mi < 2; mi++) {
                const size_t b = ((size_t)((mbase+mi)*64 + kb0 + j + 2) << 6) + (gg<<3) + tg;
                Ah01[s][mi] = ldcg2(ghHi+b);  Ah23[s][mi] = ldcg2(ghHi+b+4);
                Al01[s][mi] = ldcg2(ghLo+b);  Al23[s][mi] = ldcg2(ghLo+b+4);
            }
        }
        const int c = j % 3;
        mma16816(D[0], Ah01[c][0], Ah23[c][0], Bh0[cb]);
        mma16816(D[1], Ah01[c][0], Ah23[c][0], Bh1[cb]);
        mma16816(D[2], Ah01[c][1], Ah23[c][1], Bh0[cb]);
        mma16816(D[3], Ah01[c][1], Ah23[c][1], Bh1[cb]);
        mma16816(D[0], Ah01[c][0], Ah23[c][0], Bl0[cb]);
        mma16816(D[1], Ah01[c][0], Ah23[c][0], Bl1[cb]);
        mma16816(D[2], Ah01[c][1], Ah23[c][1], Bl0[cb]);
        mma16816(D[3], Ah01[c][1], Ah23[c][1], Bl1[cb]);
        mma16816(D[0], Al01[c][0], Al23[c][0], Bh0[cb]);
        mma16816(D[1], Al01[c][0], Al23[c][0], Bh1[cb]);
        mma16816(D[2], Al01[c][1], Al23[c][1], Bh0[cb]);
        mma16816(D[3], Al01[c][1], Al23[c][1], Bh1[cb]);
    }
}

__device__ __forceinline__ void kredw(const float (&D)[4][4], float* sred,
                                      int kw, int mbase, int lane)
{
    const int sw = lane & 7;
#pragma unroll
    for (int ui = 0; ui < 4; ui++) {
        const int u = (mbase + (ui >> 1)) * 2 + (ui & 1);
        float4* p = (float4*)&sred[((((u*32+lane) << 3) + (kw ^ sw)) << 2)];
        *p = make_float4(D[ui][0], D[ui][1], D[ui][2], D[ui][3]);
    }
}
__device__ __forceinline__ void kredr(const float* sred, int u, int lane, float r[4]) {
    const int sw = lane & 7;
    r[0] = r[1] = r[2] = r[3] = 0.f;
#pragma unroll
    for (int w = 0; w < 8; w++) {
        float4 v = *(const float4*)&sred[((((u*32+lane) << 3) + (w ^ sw)) << 2)];
        r[0] += v.x; r[1] += v.y; r[2] += v.z; r[3] += v.w;
    }
}

// ---------------------------------------------------------------------------
// pipeline-parallel recurrent, triple-buffered state. W1 split 4/4 (R12).
// counters: c1 h1 published | c2 h2 published | c5 A's W1 partial published
// ---------------------------------------------------------------------------
__global__ __launch_bounds__(TPB)
void rnn_recurrent_kernel(const float* __restrict__ bi1,
                          const float* __restrict__ bh1,
                          float* __restrict__ out,
                          int write_final)
{
    extern __shared__ u64 smem_u64[];
    u64*   sB   = smem_u64;
    float* sred = (float*)(smem_u64 + 4*SB_ENT);

    const int tid  = threadIdx.x;
    const int wid  = tid >> 5;
    const int lane = tid & 31;
    const int gg   = lane >> 2;
    const int tg   = lane & 3;
    const int grpB = (blockIdx.x >= NG);
    const int cta  = grpB ? (blockIdx.x - NG) : blockIdx.x;
    const int kw   = wid >> 1;
    const int mbase = (wid & 1) * 2;

    // A: slots 0,1 = Wh0 hi/lo; slots 2,3 = Wi1 hi/lo.
    // B: slots 0,1 = Wi1 hi/lo; slots 2,3 = Wh1 hi/lo.
#pragma unroll
    for (int mp = 0; mp < 4; mp++) {
        const int mat = grpB ? ((mp >> 1) + 1) : (mp >> 1);
        const u64* src = g_Wp[mat][mp & 1] + (size_t)cta * SB_ENT;
        u64* dst = sB + mp * SB_ENT;
        for (int i = tid * 2; i < SB_ENT; i += TPB * 2)
            *(uint4*)(dst + i) = *(const uint4*)(src + i);
    }

    const int u  = wid & 7;
    const int mt = u >> 1, nf = u & 1;
    const int m0 = mt * 16 + gg;
    const int n0 = cta * 16 + nf * 8 + tg * 2;
    const unsigned ei = (unsigned)((mt * 64 + cta) << 6) + (gg << 3) + (nf * 4 + tg);
    const unsigned pi = ((unsigned)cta << 10) + ((unsigned)u << 7) + ((unsigned)lane << 2);
    const float bias0 = bi1[n0] + bh1[n0];
    const float bias1 = bi1[n0+1] + bh1[n0+1];
    __syncthreads();

    float D[4][4], r[4];

    if (!grpB) {
        // ------------- group A: W0 (full K) + W1 first K-half -------------
        for (int t = 0; t < SEQ; t++) {
            const int rp = (t + 2) % 3, wp = t % 3;
            // prefetch P(t) early (off the epilogue critical path)
            float2 pf0, pf1;
            if (wid < 8) {
                const float* Pt = g_P + (size_t)t * BATCH * HD;
                pf0 = __ldg((const float2*)(Pt + (size_t)m0 * HD + n0));
                pf1 = __ldg((const float2*)(Pt + (size_t)(m0+8) * HD + n0));
            }
#pragma unroll
            for (int ui = 0; ui < 4; ui++)
                D[ui][0] = D[ui][1] = D[ui][2] = D[ui][3] = 0.f;
            gemm_acc<8>(D, g_h1hi[rp], g_h1lo[rp], sB, kw * 8, mbase, gg, tg);
            kredw(D, sred, kw, mbase, lane);
            // slack wait: B's epi(t-3) done -> h1[wp], g_r1[wp] reusable
            grid_wait(&g_c2, (t >= 2) ? (unsigned)(t - 2) * NG : 0u);
            __syncthreads();
            if (wid < 8) {
                kredr(sred, u, lane, r);
                float v0 = tanhf(r[0] + pf0.x), v1 = tanhf(r[1] + pf0.y);
                float v2 = tanhf(r[2] + pf1.x), v3 = tanhf(r[3] + pf1.y);
                u64 hi, lo; pack_hilo(v0, v1, v2, v3, hi, lo);
                stcg64(&g_h1hi[wp][ei], hi);
                stcg64(&g_h1lo[wp][ei], lo);
                if (write_final && t == SEQ - 1) {
                    *(float2*)&out[OUT_MAIN + (size_t)m0*HD + n0]     = make_float2(v0, v1);
                    *(float2*)&out[OUT_MAIN + (size_t)(m0+8)*HD + n0] = make_float2(v2, v3);
                }
            }
            grid_arrive(&g_c1);                      // publish h1(t)
            grid_wait(&g_c1, (unsigned)(t + 1) * NG);
#pragma unroll
            for (int ui = 0; ui < 4; ui++)
                D[ui][0] = D[ui][1] = D[ui][2] = D[ui][3] = 0.f;
            gemm_acc<4>(D, g_h1hi[wp], g_h1lo[wp], sB + 2*SB_ENT, kw * 4, mbase, gg, tg);
            kredw(D, sred, kw, mbase, lane);
            __syncthreads();
            if (wid < 8) {
                kredr(sred, u, lane, r);
                stcg4f(&g_r1[wp][pi], make_float4(r[0], r[1], r[2], r[3]));
            }
            grid_arrive(&g_c5);                      // publish W1 partial(t)
        }
    } else {
        // ------------- group B: W2 (full K) + W1 second K-half -------------
        for (int t = 0; t < SEQ; t++) {
            const int rp = (t + 2) % 3, wp = t % 3;
            grid_wait(&g_c2, (unsigned)t * NG);      // all B epi(t-1) done
#pragma unroll
            for (int ui = 0; ui < 4; ui++)
                D[ui][0] = D[ui][1] = D[ui][2] = D[ui][3] = 0.f;
            gemm_acc<8>(D, g_h2hi[rp], g_h2lo[rp], sB + 2*SB_ENT, kw * 8, mbase, gg, tg);
            grid_wait(&g_c1, (unsigned)(t + 1) * NG);// h1(t) visible
            gemm_acc<4>(D, g_h1hi[wp], g_h1lo[wp], sB, 32 + kw * 4, mbase, gg, tg);
            kredw(D, sred, kw, mbase, lane);
            grid_wait(&g_c5, (unsigned)(t + 1) * NG);// A's partial(t) ready
            __syncthreads();
            if (wid < 8) {
                kredr(sred, u, lane, r);
                const float4 pa = ldcg4f(&g_r1[wp][pi]);
                float v0 = tanhf(r[0] + pa.x + bias0), v1 = tanhf(r[1] + pa.y + bias1);
                float v2 = tanhf(r[2] + pa.z + bias0), v3 = tanhf(r[3] + pa.w + bias1);
                u64 hi, lo; pack_hilo(v0, v1, v2, v3, hi, lo);
                stcg64(&g_h2hi[wp][ei], hi);
                stcg64(&g_h2lo[wp][ei], lo);
                float* ot = out + (size_t)t * BATCH * HD;
                *(float2*)&ot[(size_t)m0*HD + n0]     = make_float2(v0, v1);
                *(float2*)&ot[(size_t)(m0+8)*HD + n0] = make_float2(v2, v3);
                if (write_final && t == SEQ - 1) {
                    float* hf = out + OUT_MAIN + (size_t)BATCH*HD;
                    *(float2*)&hf[(size_t)m0*HD + n0]     = make_float2(v0, v1);
                    *(float2*)&hf[(size_t)(m0+8)*HD + n0] = make_float2(v2, v3);
                }
            }
            grid_arrive(&g_c2);                      // publish h2(t)
        }
    }
}

// ---------------------------------------------------------------------------
extern "C" void kernel_launch(void* const* d_in, const int* in_sizes, int n_in,
                              void* d_out, int out_size) {
    const float* x   = (const float*)d_in[0];
    const float* Wi0 = (const float*)d_in[1];
    const float* bi0 = (const float*)d_in[2];
    const float* Wh0 = (const float*)d_in[3];
    const float* bh0 = (const float*)d_in[4];
    const float* Wi1 = (const float*)d_in[5];
    const float* bi1 = (const float*)d_in[6];
    const float* Wh1 = (const float*)d_in[7];
    const float* bh1 = (const float*)d_in[8];
    float* out = (float*)d_out;

    const int write_final =
        ((size_t)out_size >= OUT_MAIN + (size_t)2 * BATCH * HD) ? 1 : 0;

    cudaFuncSetAttribute(rnn_recurrent_kernel,
                         cudaFuncAttributeMaxDynamicSharedMemorySize, SMEM2_BYTES);
    cudaFuncSetAttribute(rnn_precompute_mma,
                         cudaFuncAttributeMaxDynamicSharedMemorySize, PC_SMEM);

    rnn_reset_kernel<<<256, 256>>>();
    rnn_prepw_kernel<<<(4*GW_ENT + 255)/256, 256>>>(Wh0, Wi1, Wh1, Wi0);
    rnn_xpack_kernel<<<(GX_ENT + 255)/256, 256>>>(x);
    rnn_precompute_mma<<<dim3(16, 128), 256, PC_SMEM>>>(bi0, bh0);
    rnn_recurrent_kernel<<<2*NG, TPB, SMEM2_BYTES>>>(bi1, bh1, out, write_final);
}